// round 11
// baseline (speedup 1.0000x reference)
#include <cuda_runtime.h>
#include <cuda_bf16.h>

// Fixed problem shapes
#define P_FULL   65536          // H*W
#define PN       12544          // sampled points
#define M_TGT    80             // targets
#define K_CLS    134            // classes
#define N_ROWS   400            // bs*Q
#define A_ROWS_P 896            // padded rows (14*64); 2 rows (x, sigmoid) per n
#define MTILES   14             // m-tiles of 64 rows
#define NKC      14             // split-K chunks
#define KC_U32   448            // u32 (bf16x2) per k-chunk (=896 points)
#define NSTG     7              // stages per chunk
#define JC       49             // j-chunks for prepY
#define ROW_U32  (PN / 2)       // 6272 u32 per bf16 row
#define NWORDS   (P_FULL / 32)  // 2048 bitmap words
#define D_ELEMS  (A_ROWS_P * M_TGT)   // 71680

typedef unsigned int u32;

// ---- static scratch (BSS zero-init; g_A rows >= 800 never written => zero) ----
__device__ __align__(256) __nv_bfloat16 g_A[(size_t)A_ROWS_P * PN];  // 22.5MB
__device__ __align__(256) __nv_bfloat16 g_Y[(size_t)M_TGT * PN];     // 2MB
__device__ float g_D[D_ELEMS];             // [row][m] final dot-products (atomic acc)
__device__ float g_spsum[2 * N_ROWS];
__device__ float g_sgsum[2 * N_ROWS];
__device__ int   g_ysum_i[M_TGT];
__device__ __align__(16) int g_sorted[PN]; // sampled pixels ascending

// ---------------------------------------------------------------------------
// K0: sort sampled pixels (single CTA): smem bitmap -> scan -> emit.
// Also zeroes g_ysum_i and g_D each call (required for atomic accumulation;
// deterministic across graph replays).
// ---------------------------------------------------------------------------
__global__ void __launch_bounds__(1024)
hm_sort_kernel(const int* __restrict__ point_idx) {
    __shared__ u32 bmp[NWORDS];    // 8KB
    __shared__ int sc[1024];
    const int t = threadIdx.x;

    bmp[2 * t] = 0u; bmp[2 * t + 1] = 0u;
    if (t < M_TGT) g_ysum_i[t] = 0;
    // zero g_D (71680 floats = 17920 float4)
    float4* d4 = (float4*)g_D;
#pragma unroll
    for (int i = 0; i < 17; i++) d4[t + i * 1024] = make_float4(0.f, 0.f, 0.f, 0.f);
    if (t < 17920 - 17 * 1024) d4[t + 17 * 1024] = make_float4(0.f, 0.f, 0.f, 0.f);
    __syncthreads();

#pragma unroll
    for (int i = 0; i < 13; i++) {
        int j = t + i * 1024;
        if (j < PN) {
            int p = __ldg(point_idx + j);
            atomicOr(&bmp[p >> 5], 1u << (p & 31));
        }
    }
    __syncthreads();

    u32 w0 = bmp[2 * t], w1 = bmp[2 * t + 1];
    int p0 = __popc(w0), p1 = __popc(w1);
    int c = p0 + p1;
    sc[t] = c;
    __syncthreads();
    for (int off = 1; off < 1024; off <<= 1) {
        int v = (t >= off) ? sc[t - off] : 0;
        __syncthreads();
        sc[t] += v;
        __syncthreads();
    }
    int r = sc[t] - c;   // exclusive prefix
    int base = t * 64;
    while (w0) {
        int b = __ffs(w0) - 1;
        g_sorted[r++] = base + b;
        w0 &= w0 - 1;
    }
    base += 32;
    while (w1) {
        int b = __ffs(w1) - 1;
        g_sorted[r++] = base + b;
        w1 &= w1 - 1;
    }
}

// ---------------------------------------------------------------------------
// K1: merged gather kernel.
//  blocks [0, 800):   buildA — A rows (x, sigmoid) bf16 + sp/sg sums
//  blocks [800, 1290): prepY — Y bf16 (8 m's per thread) + ysum atomics
// ---------------------------------------------------------------------------
__device__ __forceinline__ void act(float x, float& sg, float& sp) {
    float e   = __expf(-fabsf(x));
    float inv = __fdividef(1.0f, 1.0f + e);
    sg = (x >= 0.0f) ? inv : e * inv;
    sp = fmaxf(x, 0.0f) + __logf(1.0f + e);
}
__device__ __forceinline__ u32 packbf(float a, float b) {
    u32 lo = (u32)__bfloat16_as_ushort(__float2bfloat16_rn(a));
    u32 hi = (u32)__bfloat16_as_ushort(__float2bfloat16_rn(b));
    return lo | (hi << 16);
}

__global__ void __launch_bounds__(256)
hm_gather_kernel(const float* __restrict__ pred_masks,
                 const float* __restrict__ tgt_masks) {
    const int b = blockIdx.x;
    const int t = threadIdx.x;

    if (b < 2 * N_ROWS) {
        // ---------------- buildA ----------------
        const int n = b >> 1;
        const int h = b & 1;
        const float* __restrict__ xrow = pred_masks + (size_t)n * P_FULL;
        const int4* __restrict__ pidx4 = (const int4*)g_sorted;
        u32* __restrict__ ax = (u32*)(g_A + (size_t)(2 * n) * PN);
        u32* __restrict__ as = (u32*)(g_A + (size_t)(2 * n + 1) * PN);

        const int jb4 = h * 1568;
        float spsum = 0.0f, sgsum = 0.0f;

        int4 nid = __ldg(pidx4 + jb4 + t);

#pragma unroll 1
        for (int i = 0; i < 6; i++) {
            int4 id = nid;
            if (i < 5)        nid = __ldg(pidx4 + jb4 + (i + 1) * 256 + t);
            else if (t < 32)  nid = __ldg(pidx4 + jb4 + 1536 + t);

            float x0 = __ldg(xrow + id.x);
            float x1 = __ldg(xrow + id.y);
            float x2 = __ldg(xrow + id.z);
            float x3 = __ldg(xrow + id.w);
            float sg0, sp0, sg1, sp1, sg2, sp2, sg3, sp3;
            act(x0, sg0, sp0); act(x1, sg1, sp1);
            act(x2, sg2, sp2); act(x3, sg3, sp3);
            spsum += (sp0 + sp1) + (sp2 + sp3);
            sgsum += (sg0 + sg1) + (sg2 + sg3);

            int col = (jb4 + i * 256 + t) * 2;
            ax[col]     = packbf(x0, x1);
            ax[col + 1] = packbf(x2, x3);
            as[col]     = packbf(sg0, sg1);
            as[col + 1] = packbf(sg2, sg3);
        }
        if (t < 32) {
            int4 id = nid;
            float x0 = __ldg(xrow + id.x);
            float x1 = __ldg(xrow + id.y);
            float x2 = __ldg(xrow + id.z);
            float x3 = __ldg(xrow + id.w);
            float sg0, sp0, sg1, sp1, sg2, sp2, sg3, sp3;
            act(x0, sg0, sp0); act(x1, sg1, sp1);
            act(x2, sg2, sp2); act(x3, sg3, sp3);
            spsum += (sp0 + sp1) + (sp2 + sp3);
            sgsum += (sg0 + sg1) + (sg2 + sg3);
            int col = (jb4 + 1536 + t) * 2;
            ax[col]     = packbf(x0, x1);
            ax[col + 1] = packbf(x2, x3);
            as[col]     = packbf(sg0, sg1);
            as[col + 1] = packbf(sg2, sg3);
        }

        __shared__ float rp[8], rg[8];
#pragma unroll
        for (int off = 16; off > 0; off >>= 1) {
            spsum += __shfl_xor_sync(0xffffffffu, spsum, off);
            sgsum += __shfl_xor_sync(0xffffffffu, sgsum, off);
        }
        if ((t & 31) == 0) { rp[t >> 5] = spsum; rg[t >> 5] = sgsum; }
        __syncthreads();
        if (t == 0) {
            float sp = 0.0f, sg = 0.0f;
#pragma unroll
            for (int w = 0; w < 8; w++) { sp += rp[w]; sg += rg[w]; }
            g_spsum[n * 2 + h] = sp;
            g_sgsum[n * 2 + h] = sg;
        }
    } else {
        // ---------------- prepY (8 m's per thread) ----------------
        const int b2 = b - 2 * N_ROWS;
        const int c  = b2 % JC;
        const int m0 = (b2 / JC) * 8;
        const int j  = c * 256 + t;
        const int pj = __ldg(g_sorted + j);

        float v[8];
#pragma unroll
        for (int k = 0; k < 8; k++)
            v[k] = __ldg(tgt_masks + (size_t)(m0 + k) * P_FULL + pj);

        __shared__ int wc[8][8];
#pragma unroll
        for (int k = 0; k < 8; k++) {
            int on = (v[k] != 0.0f);
            g_Y[(size_t)(m0 + k) * PN + j] =
                __float2bfloat16_rn(on ? 1.0f : 0.0f);
            unsigned ball = __ballot_sync(0xffffffffu, on);
            if ((t & 31) == 0) wc[k][t >> 5] = __popc(ball);
        }
        __syncthreads();
        if (t < 8) {
            int s = 0;
#pragma unroll
            for (int w = 0; w < 8; w++) s += wc[t][w];
            atomicAdd(&g_ysum_i[m0 + t], s);   // integer: deterministic
        }
    }
}

// ---------------------------------------------------------------------------
// K2: split-K bf16 GEMM, cp.async double-buffered; epilogue accumulates
// directly into g_D[row][m] via float red.add (kills the partial round-trip).
// grid (14, 14) x 256 threads (4 m-warps x 2 n-warps).
// CTA tile 64(M) x 80(N) x 896(K points), 7 stages of 128 points.
// ---------------------------------------------------------------------------
#define SP        68
#define ABUF_U32  (64 * SP)
#define BBUF_U32  (80 * SP)
#define STAGE_U32 (ABUF_U32 + BBUF_U32)
#define SMEM_K2_BYTES (2 * STAGE_U32 * 4)   // 78336

__device__ __forceinline__ void cp16(u32* smem_dst, const u32* gsrc) {
    u32 sa = (u32)__cvta_generic_to_shared(smem_dst);
    asm volatile("cp.async.cg.shared.global [%0], [%1], 16;\n"
                 :: "r"(sa), "l"(gsrc));
}

__global__ void __launch_bounds__(256)
hm_gemm_kernel() {
    extern __shared__ u32 sh[];

    const int bm = blockIdx.x;
    const int kc = blockIdx.y;
    const int t  = threadIdx.x;
    const int warpid = t >> 5;
    const int lane = t & 31;
    const int g    = lane >> 2;
    const int tid4 = lane & 3;
    const int mw   = warpid & 3;
    const int nw   = warpid >> 2;

    const u32* __restrict__ A32 = (const u32*)g_A;
    const u32* __restrict__ Y32 = (const u32*)g_Y;
    const int R      = bm * 64;
    const int kwbase = kc * KC_U32;

#define ISSUE_STAGE(stg)                                                      \
    do {                                                                      \
        u32* dst = sh + ((stg) & 1) * STAGE_U32;                              \
        const int kw = kwbase + (stg) * 64;                                   \
        _Pragma("unroll")                                                     \
        for (int i = 0; i < 9; i++) {                                         \
            int id = t + 256 * i;                                             \
            if (id < 1024) {                                                  \
                int r = id >> 4, c = (id & 15) * 4;                           \
                cp16(dst + r * SP + c,                                        \
                     A32 + (size_t)(R + r) * ROW_U32 + kw + c);               \
            } else {                                                          \
                int id2 = id - 1024;                                          \
                int r = id2 >> 4, c = (id2 & 15) * 4;                         \
                cp16(dst + ABUF_U32 + r * SP + c,                             \
                     Y32 + (size_t)r * ROW_U32 + kw + c);                     \
            }                                                                 \
        }                                                                     \
        asm volatile("cp.async.commit_group;\n");                             \
    } while (0)

    float d[5][4];
#pragma unroll
    for (int nt = 0; nt < 5; nt++)
#pragma unroll
        for (int q = 0; q < 4; q++) d[nt][q] = 0.0f;

    ISSUE_STAGE(0);

#pragma unroll 1
    for (int stg = 0; stg < NSTG; stg++) {
        if (stg + 1 < NSTG) {
            ISSUE_STAGE(stg + 1);
            asm volatile("cp.async.wait_group 1;\n");
        } else {
            asm volatile("cp.async.wait_group 0;\n");
        }
        __syncthreads();

        const u32* As = sh + (stg & 1) * STAGE_U32;
        const u32* Bs = As + ABUF_U32;
        const int wrow = mw * 16;
#pragma unroll
        for (int ks = 0; ks < 8; ks++) {
            const int kcol = ks * 8;
            const u32* pa = As + (wrow + g) * SP + kcol + tid4;
            u32 a0 = pa[0];
            u32 a1 = pa[8 * SP];
            u32 a2 = pa[4];
            u32 a3 = pa[8 * SP + 4];
#pragma unroll
            for (int nt = 0; nt < 5; nt++) {
                const u32* pb = Bs + (nw * 40 + nt * 8 + g) * SP + kcol + tid4;
                u32 b0 = pb[0];
                u32 b1 = pb[4];
                asm volatile(
                    "mma.sync.aligned.m16n8k16.row.col.f32.bf16.bf16.f32 "
                    "{%0,%1,%2,%3}, {%4,%5,%6,%7}, {%8,%9}, {%0,%1,%2,%3};"
                    : "+f"(d[nt][0]), "+f"(d[nt][1]), "+f"(d[nt][2]), "+f"(d[nt][3])
                    : "r"(a0), "r"(a1), "r"(a2), "r"(a3), "r"(b0), "r"(b1));
            }
        }
        __syncthreads();
    }

    // epilogue: reduce into g_D[row][m] (REDG, no return)
    const int row0 = R + mw * 16 + g;
#pragma unroll
    for (int nt = 0; nt < 5; nt++) {
        int ncol = nw * 40 + nt * 8 + tid4 * 2;
        atomicAdd(&g_D[row0 * M_TGT + ncol],           d[nt][0]);
        atomicAdd(&g_D[row0 * M_TGT + ncol + 1],       d[nt][1]);
        atomicAdd(&g_D[(row0 + 8) * M_TGT + ncol],     d[nt][2]);
        atomicAdd(&g_D[(row0 + 8) * M_TGT + ncol + 1], d[nt][3]);
    }
}

// ---------------------------------------------------------------------------
// K3: final — softmax + cost assembly; g_D reads now contiguous.
// grid 400 x 256 threads.
// ---------------------------------------------------------------------------
__global__ void __launch_bounds__(256)
hm_final_kernel(const float* __restrict__ pred_logits,
                const int*   __restrict__ tgt_labels,
                float*       __restrict__ out) {
    const int n = blockIdx.x;
    const int t = threadIdx.x;

    __shared__ float lg[K_CLS];
    __shared__ float rr[128];
    __shared__ float s_mx, s_inv;

    if (t < K_CLS) lg[t] = __ldg(pred_logits + (size_t)n * K_CLS + t);
    __syncthreads();

    if (t < 128) {
        float v = lg[t];
        if (t < K_CLS - 128) v = fmaxf(v, lg[t + 128]);
        rr[t] = v;
    }
    __syncthreads();
#pragma unroll
    for (int s = 64; s > 0; s >>= 1) {
        if (t < s) rr[t] = fmaxf(rr[t], rr[t + s]);
        __syncthreads();
    }
    if (t == 0) s_mx = rr[0];
    __syncthreads();
    if (t < 128) {
        float v = __expf(lg[t] - s_mx);
        if (t < K_CLS - 128) v += __expf(lg[t + 128] - s_mx);
        rr[t] = v;
    }
    __syncthreads();
#pragma unroll
    for (int s = 64; s > 0; s >>= 1) {
        if (t < s) rr[t] += rr[t + s];
        __syncthreads();
    }
    if (t == 0) s_inv = __fdividef(1.0f, rr[0]);
    __syncthreads();

    if (t < M_TGT) {
        float xy = __ldg(g_D + (2 * n) * M_TGT + t);
        float sy = __ldg(g_D + (2 * n + 1) * M_TGT + t);
        float sp = g_spsum[2 * n] + g_spsum[2 * n + 1];
        float sg = g_sgsum[2 * n] + g_sgsum[2 * n + 1];
        float yc = (float)__ldg(g_ysum_i + t);

        int lbl = __ldg(tgt_labels + t);
        lbl = min(max(lbl, 0), K_CLS - 1);
        float p = __expf(lg[lbl] - s_mx) * s_inv;

        const float invPn = 1.0f / (float)PN;
        float cost_class = -p;
        float cost_mask  = (sp - xy) * invPn;
        float cost_dice  = 1.0f - (2.0f * sy + 1.0f) / (sg + yc + 1.0f);
        out[(size_t)n * M_TGT + t] =
            2.0f * cost_class + 5.0f * cost_mask + 5.0f * cost_dice;
    }
}

// ---------------------------------------------------------------------------
// Inputs (metadata order):
//   d_in[0] pred_logits f32 (4,100,134)
//   d_in[1] pred_masks  f32 (4,100,256,256)
//   d_in[2] tgt_labels  i32 (80)
//   d_in[3] tgt_masks   f32 (80,256,256)
//   d_in[4] point_idx   i32 (12544)
// out: f32 (4,100,80)
// ---------------------------------------------------------------------------
extern "C" void kernel_launch(void* const* d_in, const int* in_sizes, int n_in,
                              void* d_out, int out_size) {
    const float* pred_logits = (const float*)d_in[0];
    const float* pred_masks  = (const float*)d_in[1];
    const int*   tgt_labels  = (const int*)  d_in[2];
    const float* tgt_masks   = (const float*)d_in[3];
    const int*   point_idx   = (const int*)  d_in[4];
    float* out = (float*)d_out;

    static int smem_set = 0;
    if (!smem_set) {
        cudaFuncSetAttribute(hm_gemm_kernel,
                             cudaFuncAttributeMaxDynamicSharedMemorySize,
                             SMEM_K2_BYTES);
        smem_set = 1;
    }

    hm_sort_kernel<<<1, 1024>>>(point_idx);
    hm_gather_kernel<<<2 * N_ROWS + JC * (M_TGT / 8), 256>>>(pred_masks,
                                                             tgt_masks);
    dim3 gg(MTILES, NKC);
    hm_gemm_kernel<<<gg, 256, SMEM_K2_BYTES>>>();
    hm_final_kernel<<<N_ROWS, 256>>>(pred_logits, tgt_labels, out);
}